// round 1
// baseline (speedup 1.0000x reference)
#include <cuda_runtime.h>

#define NQ 2048
#define NK 2048
#define NH 8
#define DH 64

// Scratch: exp(sq) and exp(sk), 2048x8 floats each (64 KB each).
__device__ float g_esq[NQ * NH];
__device__ float g_esk[NK * NH];

// One block per row (first NQ blocks -> q, next NK -> k).
// 256 threads = 8 warps; warp h reduces the 64-elem dot for head h.
__global__ void __launch_bounds__(256) proj_kernel(
    const float* __restrict__ q,
    const float* __restrict__ k,
    const float* __restrict__ attn)
{
    int row = blockIdx.x;
    const float* src;
    int koff;
    float* dst;
    if (row < NQ) {
        src  = q + (size_t)row * (NH * DH);
        koff = 0;
        dst  = g_esq + row * NH;
    } else {
        int r = row - NQ;
        src  = k + (size_t)r * (NH * DH);
        koff = DH;
        dst  = g_esk + r * NH;
    }

    int tid  = threadIdx.x;       // 0..255
    int h    = tid >> 5;          // warp id = head id
    int lane = tid & 31;

    // Row is 512 contiguous floats: [h][d]. Thread covers elems 2*tid, 2*tid+1.
    float2 v = ((const float2*)src)[tid];
    // attn layout: (1, NH, 2*DH): a_q at [h][0:64], a_k at [h][64:128]
    float2 c = *(const float2*)(attn + h * (2 * DH) + koff + lane * 2);

    float s = v.x * c.x + v.y * c.y;
    #pragma unroll
    for (int off = 16; off; off >>= 1)
        s += __shfl_xor_sync(0xffffffffu, s, off);

    if (lane == 0) dst[h] = __expf(s);
}

// Grid: (NK/256, NQ). One thread per (q,k) pair; writes 8 contiguous floats.
__global__ void __launch_bounds__(256) softmax_kernel(float* __restrict__ out)
{
    int qi = blockIdx.y;
    int kk = blockIdx.x * 256 + threadIdx.x;

    __shared__ float s_eq[NH];
    if (threadIdx.x < NH) s_eq[threadIdx.x] = g_esq[qi * NH + threadIdx.x];
    __syncthreads();

    float e0 = s_eq[0], e1 = s_eq[1], e2 = s_eq[2], e3 = s_eq[3];
    float e4 = s_eq[4], e5 = s_eq[5], e6 = s_eq[6], e7 = s_eq[7];

    const float4* ekp = (const float4*)(g_esk + kk * NH);
    float4 a = ekp[0];
    float4 b = ekp[1];

    // exp(relu(sq+sk)) == max(exp(sq)*exp(sk), 1)
    float p0 = fmaxf(e0 * a.x, 1.0f);
    float p1 = fmaxf(e1 * a.y, 1.0f);
    float p2 = fmaxf(e2 * a.z, 1.0f);
    float p3 = fmaxf(e3 * a.w, 1.0f);
    float p4 = fmaxf(e4 * b.x, 1.0f);
    float p5 = fmaxf(e5 * b.y, 1.0f);
    float p6 = fmaxf(e6 * b.z, 1.0f);
    float p7 = fmaxf(e7 * b.w, 1.0f);

    float sum = ((p0 + p1) + (p2 + p3)) + ((p4 + p5) + (p6 + p7));
    float inv = __fdividef(1.0f, sum);

    float4 o0 = make_float4(p0 * inv, p1 * inv, p2 * inv, p3 * inv);
    float4 o1 = make_float4(p4 * inv, p5 * inv, p6 * inv, p7 * inv);

    float4* op = (float4*)(out + ((size_t)qi * NK + kk) * NH);
    op[0] = o0;
    op[1] = o1;
}

extern "C" void kernel_launch(void* const* d_in, const int* in_sizes, int n_in,
                              void* d_out, int out_size)
{
    const float* q    = (const float*)d_in[0];
    const float* k    = (const float*)d_in[1];
    const float* attn = (const float*)d_in[2];
    float* out = (float*)d_out;

    proj_kernel<<<NQ + NK, 256>>>(q, k, attn);

    dim3 grid(NK / 256, NQ);
    softmax_kernel<<<grid, 256>>>(out);
}